// round 2
// baseline (speedup 1.0000x reference)
#include <cuda_runtime.h>

#define N_NODES 50000
#define N_EDGES 600000
#define HID 128
#define NODE_DIM 64
#define EDGE_DIM 16
#define NLAYERS 3
#define NGRAPHS 256
#define BN_EPS 1e-5f

// ---------------- scratch (device globals; no allocations allowed) ----------
__device__ float g_h[N_NODES * HID];     // node features (post-activation)
__device__ float g_agg[N_NODES * HID];   // scatter-add accumulator
__device__ float g_z[N_NODES * HID];     // pre-BN MLP output
__device__ float g_stats[2 * HID];       // [0:128) column sums, [128:256) sumsq
__device__ float g_pool[NGRAPHS * HID];  // pooled graph features

__device__ __forceinline__ void red_add_v4(float* p, float4 v) {
    asm volatile("red.global.add.v4.f32 [%0], {%1,%2,%3,%4};"
                 :: "l"(p), "f"(v.x), "f"(v.y), "f"(v.z), "f"(v.w) : "memory");
}

// ---------------- zero kernels ----------------------------------------------
__global__ void zero_agg_stats_kernel() {
    int i = blockIdx.x * blockDim.x + threadIdx.x;
    int stride = gridDim.x * blockDim.x;
    float4* a4 = reinterpret_cast<float4*>(g_agg);
    const int n4 = N_NODES * HID / 4;
    float4 z = make_float4(0.f, 0.f, 0.f, 0.f);
    for (int k = i; k < n4; k += stride) a4[k] = z;
    if (i < 2 * HID) g_stats[i] = 0.f;
}

__global__ void zero_pool_kernel() {
    int i = blockIdx.x * blockDim.x + threadIdx.x;
    if (i < NGRAPHS * HID) g_pool[i] = 0.f;
}

// ---------------- node encoder: h = x @ node_w + node_b ---------------------
__global__ void encoder_kernel(const float* __restrict__ x,
                               const float* __restrict__ W,
                               const float* __restrict__ b) {
    __shared__ float sW[NODE_DIM * HID];
    for (int i = threadIdx.x; i < NODE_DIM * HID; i += blockDim.x) sW[i] = W[i];
    __syncthreads();
    int lane = threadIdx.x & 31;
    int warp = (blockIdx.x * blockDim.x + threadIdx.x) >> 5;
    int nw = (gridDim.x * blockDim.x) >> 5;
    float4 bb = reinterpret_cast<const float4*>(b)[lane];
    for (int n = warp; n < N_NODES; n += nw) {
        const float4* xr = reinterpret_cast<const float4*>(x + (size_t)n * NODE_DIM);
        float4 acc = bb;
        #pragma unroll
        for (int kk = 0; kk < NODE_DIM / 4; kk++) {
            float4 xv = xr[kk];
            float xa[4] = {xv.x, xv.y, xv.z, xv.w};
            #pragma unroll
            for (int j = 0; j < 4; j++) {
                float4 w = *reinterpret_cast<const float4*>(&sW[(4 * kk + j) * HID + 4 * lane]);
                acc.x += xa[j] * w.x;
                acc.y += xa[j] * w.y;
                acc.z += xa[j] * w.z;
                acc.w += xa[j] * w.w;
            }
        }
        reinterpret_cast<float4*>(g_h + (size_t)n * HID)[lane] = acc;
    }
}

// ---------------- message + scatter: agg[dst] += relu(h[src] + ea) ----------
__global__ void message_kernel(const float* __restrict__ eattr,
                               const int* __restrict__ eidx,
                               const float* __restrict__ eW,
                               const float* __restrict__ eb) {
    __shared__ float sW[EDGE_DIM * HID];
    __shared__ float sb[HID];
    for (int i = threadIdx.x; i < EDGE_DIM * HID; i += blockDim.x) sW[i] = eW[i];
    if (threadIdx.x < HID) sb[threadIdx.x] = eb[threadIdx.x];
    __syncthreads();
    int lane = threadIdx.x & 31;
    int warp = (blockIdx.x * blockDim.x + threadIdx.x) >> 5;
    int nw = (gridDim.x * blockDim.x) >> 5;
    float4 bb = reinterpret_cast<const float4*>(sb)[lane];
    for (int e = warp; e < N_EDGES; e += nw) {
        int src = eidx[e];
        int dst = eidx[N_EDGES + e];
        float4 acc = bb;
        const float4* ar = reinterpret_cast<const float4*>(eattr + (size_t)e * EDGE_DIM);
        #pragma unroll
        for (int kk = 0; kk < EDGE_DIM / 4; kk++) {
            float4 av = ar[kk];
            float xa[4] = {av.x, av.y, av.z, av.w};
            #pragma unroll
            for (int j = 0; j < 4; j++) {
                float4 w = *reinterpret_cast<const float4*>(&sW[(4 * kk + j) * HID + 4 * lane]);
                acc.x += xa[j] * w.x;
                acc.y += xa[j] * w.y;
                acc.z += xa[j] * w.z;
                acc.w += xa[j] * w.w;
            }
        }
        float4 hv = reinterpret_cast<const float4*>(g_h + (size_t)src * HID)[lane];
        float4 m;
        m.x = fmaxf(hv.x + acc.x, 0.f);
        m.y = fmaxf(hv.y + acc.y, 0.f);
        m.z = fmaxf(hv.z + acc.z, 0.f);
        m.w = fmaxf(hv.w + acc.w, 0.f);
        red_add_v4(g_agg + (size_t)dst * HID + 4 * lane, m);
    }
}

// ---------------- per-layer MLP: z = relu((h+agg)@W1+b1)@W2+b2, + BN stats --
// dynamic smem layout (floats): W1[16384] W2[16384] In[4096] T[4096] B1[128] B2[128]
#define MLP_SMEM_FLOATS (2 * HID * HID + 2 * 32 * HID + 2 * HID)
__global__ void mlp_kernel(const float* __restrict__ W1, const float* __restrict__ B1,
                           const float* __restrict__ W2, const float* __restrict__ B2) {
    extern __shared__ float sm[];
    float* sW1 = sm;
    float* sW2 = sm + HID * HID;
    float* sIn = sm + 2 * HID * HID;
    float* sT  = sIn + 32 * HID;
    float* sB1 = sT + 32 * HID;
    float* sB2 = sB1 + HID;

    int tid = threadIdx.x;
    for (int i = tid; i < HID * HID; i += 256) { sW1[i] = W1[i]; sW2[i] = W2[i]; }
    if (tid < HID) { sB1[tid] = B1[tid]; sB2[tid] = B2[tid]; }
    __syncthreads();

    int rpb = (N_NODES + gridDim.x - 1) / gridDim.x;
    int base = blockIdx.x * rpb;
    int rend = min(base + rpb, N_NODES);

    int c0 = (tid & 31) * 4;
    int r0 = (tid >> 5) * 4;

    float ls[4] = {0.f, 0.f, 0.f, 0.f};
    float lss[4] = {0.f, 0.f, 0.f, 0.f};

    for (int rbase = base; rbase < rend; rbase += 32) {
        // load input tile (h + agg)
        for (int i = tid; i < 32 * HID; i += 256) {
            int r = i >> 7;
            int cc = i & 127;
            int row = rbase + r;
            sIn[i] = (row < rend) ? g_h[(size_t)row * HID + cc] + g_agg[(size_t)row * HID + cc]
                                  : 0.f;
        }
        __syncthreads();

        // stage 1: T = relu(In @ W1 + b1)
        float acc[4][4];
        #pragma unroll
        for (int i = 0; i < 4; i++)
            #pragma unroll
            for (int j = 0; j < 4; j++) acc[i][j] = sB1[c0 + j];
        for (int k = 0; k < HID; k++) {
            float4 w = *reinterpret_cast<const float4*>(&sW1[k * HID + c0]);
            #pragma unroll
            for (int i = 0; i < 4; i++) {
                float a = sIn[(r0 + i) * HID + k];
                acc[i][0] += a * w.x;
                acc[i][1] += a * w.y;
                acc[i][2] += a * w.z;
                acc[i][3] += a * w.w;
            }
        }
        #pragma unroll
        for (int i = 0; i < 4; i++) {
            float4 t;
            t.x = fmaxf(acc[i][0], 0.f);
            t.y = fmaxf(acc[i][1], 0.f);
            t.z = fmaxf(acc[i][2], 0.f);
            t.w = fmaxf(acc[i][3], 0.f);
            *reinterpret_cast<float4*>(&sT[(r0 + i) * HID + c0]) = t;
        }
        __syncthreads();

        // stage 2: z = T @ W2 + b2
        #pragma unroll
        for (int i = 0; i < 4; i++)
            #pragma unroll
            for (int j = 0; j < 4; j++) acc[i][j] = sB2[c0 + j];
        for (int k = 0; k < HID; k++) {
            float4 w = *reinterpret_cast<const float4*>(&sW2[k * HID + c0]);
            #pragma unroll
            for (int i = 0; i < 4; i++) {
                float a = sT[(r0 + i) * HID + k];
                acc[i][0] += a * w.x;
                acc[i][1] += a * w.y;
                acc[i][2] += a * w.z;
                acc[i][3] += a * w.w;
            }
        }
        #pragma unroll
        for (int i = 0; i < 4; i++) {
            int row = rbase + r0 + i;
            if (row < rend) {
                float4 v = make_float4(acc[i][0], acc[i][1], acc[i][2], acc[i][3]);
                *reinterpret_cast<float4*>(&g_z[(size_t)row * HID + c0]) = v;
                #pragma unroll
                for (int j = 0; j < 4; j++) {
                    ls[j] += acc[i][j];
                    lss[j] += acc[i][j] * acc[i][j];
                }
            }
        }
        __syncthreads();
    }

    #pragma unroll
    for (int j = 0; j < 4; j++) {
        atomicAdd(&g_stats[c0 + j], ls[j]);
        atomicAdd(&g_stats[HID + c0 + j], lss[j]);
    }
}

// ---------------- BN finalize + apply + relu -> h ---------------------------
__global__ void bn_kernel(const float* __restrict__ gamma,
                          const float* __restrict__ beta) {
    int i = blockIdx.x * blockDim.x + threadIdx.x;  // float4 index
    const int n4 = N_NODES * HID / 4;
    if (i >= n4) return;
    int c0 = (i & 31) * 4;
    float4 v = reinterpret_cast<const float4*>(g_z)[i];
    float va[4] = {v.x, v.y, v.z, v.w};
    float out[4];
    const float invN = 1.0f / (float)N_NODES;
    #pragma unroll
    for (int j = 0; j < 4; j++) {
        int c = c0 + j;
        float mean = g_stats[c] * invN;
        float var = g_stats[HID + c] * invN - mean * mean;
        float rstd = rsqrtf(var + BN_EPS);
        float o = gamma[c] * (va[j] - mean) * rstd + beta[c];
        out[j] = fmaxf(o, 0.f);
    }
    reinterpret_cast<float4*>(g_h)[i] = make_float4(out[0], out[1], out[2], out[3]);
}

// ---------------- global add pool -------------------------------------------
__global__ void pool_kernel(const int* __restrict__ batch) {
    int i = blockIdx.x * blockDim.x + threadIdx.x;  // one thread per (node, 4cols)
    if (i >= N_NODES * 32) return;
    int n = i >> 5;
    int q = i & 31;
    int gi = batch[n];
    float4 v = reinterpret_cast<const float4*>(g_h + (size_t)n * HID)[q];
    red_add_v4(g_pool + (size_t)gi * HID + 4 * q, v);
}

// ---------------- head: out = relu(g@W1+b1)@W2+b2 ---------------------------
__global__ void head_kernel(const float* __restrict__ w1, const float* __restrict__ b1,
                            const float* __restrict__ w2, const float* __restrict__ b2,
                            float* __restrict__ out) {
    __shared__ float srow[HID];
    __shared__ float st[HID];
    int gi = blockIdx.x;
    int c = threadIdx.x;
    srow[c] = g_pool[(size_t)gi * HID + c];
    __syncthreads();
    float acc = b1[c];
    for (int k = 0; k < HID; k++) acc += srow[k] * w1[k * HID + c];
    st[c] = fmaxf(acc, 0.f);
    __syncthreads();
    if (c < 2) {
        float o = b2[c];
        for (int k = 0; k < HID; k++) o += st[k] * w2[k * 2 + c];
        out[gi * 2 + c] = o;
    }
}

// ---------------- launch -----------------------------------------------------
extern "C" void kernel_launch(void* const* d_in, const int* in_sizes, int n_in,
                              void* d_out, int out_size) {
    const float* x        = (const float*)d_in[0];
    const int*   eidx     = (const int*)d_in[1];
    const float* eattr    = (const float*)d_in[2];
    const int*   batch    = (const int*)d_in[3];
    const float* node_w   = (const float*)d_in[4];
    const float* node_b   = (const float*)d_in[5];
    const float* edge_w   = (const float*)d_in[6];
    const float* edge_b   = (const float*)d_in[7];
    const float* mlp_w1   = (const float*)d_in[8];
    const float* mlp_b1   = (const float*)d_in[9];
    const float* mlp_w2   = (const float*)d_in[10];
    const float* mlp_b2   = (const float*)d_in[11];
    const float* bn_gamma = (const float*)d_in[12];
    const float* bn_beta  = (const float*)d_in[13];
    const float* head_w1  = (const float*)d_in[14];
    const float* head_b1  = (const float*)d_in[15];
    const float* head_w2  = (const float*)d_in[16];
    const float* head_b2  = (const float*)d_in[17];
    float* out = (float*)d_out;

    const int mlp_smem = MLP_SMEM_FLOATS * (int)sizeof(float);
    cudaFuncSetAttribute(mlp_kernel, cudaFuncAttributeMaxDynamicSharedMemorySize, mlp_smem);

    // node encoder -> g_h
    encoder_kernel<<<512, 256>>>(x, node_w, node_b);

    for (int l = 0; l < NLAYERS; l++) {
        zero_agg_stats_kernel<<<2048, 256>>>();
        message_kernel<<<2048, 256>>>(eattr, eidx, edge_w, edge_b);
        mlp_kernel<<<148, 256, mlp_smem>>>(mlp_w1 + (size_t)l * HID * HID,
                                           mlp_b1 + (size_t)l * HID,
                                           mlp_w2 + (size_t)l * HID * HID,
                                           mlp_b2 + (size_t)l * HID);
        bn_kernel<<<(N_NODES * HID / 4 + 255) / 256, 256>>>(bn_gamma + (size_t)l * HID,
                                                            bn_beta + (size_t)l * HID);
    }

    zero_pool_kernel<<<(NGRAPHS * HID + 255) / 256, 256>>>();
    pool_kernel<<<(N_NODES * 32 + 255) / 256, 256>>>(batch);
    head_kernel<<<NGRAPHS, HID>>>(head_w1, head_b1, head_w2, head_b2, out);
}

// round 3
// speedup vs baseline: 1.8473x; 1.8473x over previous
#include <cuda_runtime.h>

#define N_NODES 50000
#define N_EDGES 600000
#define HID 128
#define NODE_DIM 64
#define EDGE_DIM 16
#define NLAYERS 3
#define NGRAPHS 256
#define BN_EPS 1e-5f

// ---------------- scratch (device globals; no allocations allowed) ----------
__device__ float g_h[N_NODES * HID];       // node features (post-activation)
__device__ float g_zin[N_NODES * HID];     // h + agg (MLP input)
__device__ float g_z[N_NODES * HID];       // pre-BN MLP output
__device__ float g_ea[N_EDGES * HID];      // encoded edge features (layer-invariant)
__device__ float g_stats[2 * HID];         // column sums / sumsq
__device__ float g_pool[NGRAPHS * HID];    // pooled graph features
// CSR by destination
__device__ int g_cnt[N_NODES];
__device__ int g_off[N_NODES + 1];
__device__ int g_cur[N_NODES];
__device__ int g_csr_src[N_EDGES];
__device__ int g_csr_eid[N_EDGES];

__device__ __forceinline__ void red_add_v4(float* p, float4 v) {
    asm volatile("red.global.add.v4.f32 [%0], {%1,%2,%3,%4};"
                 :: "l"(p), "f"(v.x), "f"(v.y), "f"(v.z), "f"(v.w) : "memory");
}

// ---------------- small zero kernels ----------------------------------------
__global__ void zero_cnt_kernel() {
    int i = blockIdx.x * blockDim.x + threadIdx.x;
    if (i < N_NODES) g_cnt[i] = 0;
}
__global__ void zero_stats_kernel() {
    int i = threadIdx.x;
    if (i < 2 * HID) g_stats[i] = 0.f;
}
__global__ void zero_pool_kernel() {
    int i = blockIdx.x * blockDim.x + threadIdx.x;
    if (i < NGRAPHS * HID) g_pool[i] = 0.f;
}

// ---------------- CSR build --------------------------------------------------
__global__ void csr_count_kernel(const int* __restrict__ eidx) {
    int e = blockIdx.x * blockDim.x + threadIdx.x;
    if (e < N_EDGES) atomicAdd(&g_cnt[eidx[N_EDGES + e]], 1);
}

__global__ void csr_scan_kernel() {  // single block, 1024 threads
    __shared__ int ssum[1024];
    int t = threadIdx.x;
    const int CH = (N_NODES + 1023) / 1024;
    int beg = t * CH;
    int end = min(beg + CH, N_NODES);
    int s = 0;
    for (int i = beg; i < end; i++) s += g_cnt[i];
    ssum[t] = s;
    __syncthreads();
    for (int off = 1; off < 1024; off <<= 1) {
        int v = (t >= off) ? ssum[t - off] : 0;
        __syncthreads();
        ssum[t] += v;
        __syncthreads();
    }
    int run = (t == 0) ? 0 : ssum[t - 1];
    for (int i = beg; i < end; i++) {
        g_off[i] = run;
        g_cur[i] = run;
        run += g_cnt[i];
    }
    if (t == 1023) g_off[N_NODES] = ssum[1023];
}

__global__ void csr_fill_kernel(const int* __restrict__ eidx) {
    int e = blockIdx.x * blockDim.x + threadIdx.x;
    if (e >= N_EDGES) return;
    int dst = eidx[N_EDGES + e];
    int slot = atomicAdd(&g_cur[dst], 1);
    g_csr_src[slot] = eidx[e];
    g_csr_eid[slot] = e;
}

// ---------------- node encoder: h = x @ node_w + node_b ---------------------
__global__ void encoder_kernel(const float* __restrict__ x,
                               const float* __restrict__ W,
                               const float* __restrict__ b) {
    __shared__ float sW[NODE_DIM * HID];
    for (int i = threadIdx.x; i < NODE_DIM * HID; i += blockDim.x) sW[i] = W[i];
    __syncthreads();
    int lane = threadIdx.x & 31;
    int warp = (blockIdx.x * blockDim.x + threadIdx.x) >> 5;
    int nw = (gridDim.x * blockDim.x) >> 5;
    float4 bb = reinterpret_cast<const float4*>(b)[lane];
    for (int n = warp; n < N_NODES; n += nw) {
        const float4* xr = reinterpret_cast<const float4*>(x + (size_t)n * NODE_DIM);
        float4 acc = bb;
        #pragma unroll
        for (int kk = 0; kk < NODE_DIM / 4; kk++) {
            float4 xv = xr[kk];
            float xa[4] = {xv.x, xv.y, xv.z, xv.w};
            #pragma unroll
            for (int j = 0; j < 4; j++) {
                float4 w = *reinterpret_cast<const float4*>(&sW[(4 * kk + j) * HID + 4 * lane]);
                acc.x += xa[j] * w.x;
                acc.y += xa[j] * w.y;
                acc.z += xa[j] * w.z;
                acc.w += xa[j] * w.w;
            }
        }
        reinterpret_cast<float4*>(g_h + (size_t)n * HID)[lane] = acc;
    }
}

// ---------------- edge encoder (ONCE): ea = edge_attr @ edge_w + edge_b -----
__global__ void edge_encoder_kernel(const float* __restrict__ eattr,
                                    const float* __restrict__ W,
                                    const float* __restrict__ b) {
    __shared__ float sW[EDGE_DIM * HID];
    __shared__ float sb[HID];
    for (int i = threadIdx.x; i < EDGE_DIM * HID; i += blockDim.x) sW[i] = W[i];
    if (threadIdx.x < HID) sb[threadIdx.x] = b[threadIdx.x];
    __syncthreads();
    int lane = threadIdx.x & 31;
    int warp = (blockIdx.x * blockDim.x + threadIdx.x) >> 5;
    int nw = (gridDim.x * blockDim.x) >> 5;
    float4 bb = reinterpret_cast<const float4*>(sb)[lane];
    for (int e = warp; e < N_EDGES; e += nw) {
        const float4* ar = reinterpret_cast<const float4*>(eattr + (size_t)e * EDGE_DIM);
        float4 acc = bb;
        #pragma unroll
        for (int kk = 0; kk < EDGE_DIM / 4; kk++) {
            float4 av = ar[kk];
            float xa[4] = {av.x, av.y, av.z, av.w};
            #pragma unroll
            for (int j = 0; j < 4; j++) {
                float4 w = *reinterpret_cast<const float4*>(&sW[(4 * kk + j) * HID + 4 * lane]);
                acc.x += xa[j] * w.x;
                acc.y += xa[j] * w.y;
                acc.z += xa[j] * w.z;
                acc.w += xa[j] * w.w;
            }
        }
        reinterpret_cast<float4*>(g_ea + (size_t)e * HID)[lane] = acc;
    }
}

// ---------------- aggregation: zin[n] = h[n] + sum_{e->n} relu(h[src]+ea[e])
__global__ void agg_kernel() {
    int lane = threadIdx.x & 31;
    int warp = (blockIdx.x * blockDim.x + threadIdx.x) >> 5;
    int nw = (gridDim.x * blockDim.x) >> 5;
    for (int n = warp; n < N_NODES; n += nw) {
        float4 acc = reinterpret_cast<const float4*>(g_h + (size_t)n * HID)[lane];
        int s = __ldg(&g_off[n]);
        int e = __ldg(&g_off[n + 1]);
        for (int idx = s; idx < e; idx++) {
            int src = __ldg(&g_csr_src[idx]);
            int eid = __ldg(&g_csr_eid[idx]);
            float4 hv = reinterpret_cast<const float4*>(g_h + (size_t)src * HID)[lane];
            float4 ev = reinterpret_cast<const float4*>(g_ea + (size_t)eid * HID)[lane];
            acc.x += fmaxf(hv.x + ev.x, 0.f);
            acc.y += fmaxf(hv.y + ev.y, 0.f);
            acc.z += fmaxf(hv.z + ev.z, 0.f);
            acc.w += fmaxf(hv.w + ev.w, 0.f);
        }
        reinterpret_cast<float4*>(g_zin + (size_t)n * HID)[lane] = acc;
    }
}

// ---------------- per-layer MLP: z = relu(zin@W1+b1)@W2+b2, + BN stats ------
// dyn smem (floats): W1[16384] W2[16384] In[8192] T[8192] B1[128] B2[128]
#define TROWS 64
#define MLP_THREADS 512
#define MLP_SMEM_FLOATS (2 * HID * HID + 2 * TROWS * HID + 2 * HID)
__global__ __launch_bounds__(MLP_THREADS, 1)
void mlp_kernel(const float* __restrict__ W1, const float* __restrict__ B1,
                const float* __restrict__ W2, const float* __restrict__ B2) {
    extern __shared__ float sm[];
    float* sW1 = sm;
    float* sW2 = sm + HID * HID;
    float* sIn = sm + 2 * HID * HID;
    float* sT  = sIn + TROWS * HID;
    float* sB1 = sT + TROWS * HID;
    float* sB2 = sB1 + HID;

    int tid = threadIdx.x;
    for (int i = tid; i < HID * HID; i += MLP_THREADS) { sW1[i] = W1[i]; sW2[i] = W2[i]; }
    if (tid < HID) { sB1[tid] = B1[tid]; sB2[tid] = B2[tid]; }
    __syncthreads();

    int rpb = (N_NODES + gridDim.x - 1) / gridDim.x;
    int base = blockIdx.x * rpb;
    int rend = min(base + rpb, N_NODES);

    int c0 = (tid & 31) * 4;
    int r0 = (tid >> 5) * 4;

    float ls[4] = {0.f, 0.f, 0.f, 0.f};
    float lss[4] = {0.f, 0.f, 0.f, 0.f};

    for (int rbase = base; rbase < rend; rbase += TROWS) {
        // load input tile
        for (int i = tid; i < TROWS * HID / 4; i += MLP_THREADS) {
            int r = i >> 5;           // row within tile (128/4 = 32 float4 per row)
            int q = i & 31;
            int row = rbase + r;
            float4 v = make_float4(0.f, 0.f, 0.f, 0.f);
            if (row < rend) v = reinterpret_cast<const float4*>(g_zin + (size_t)row * HID)[q];
            reinterpret_cast<float4*>(sIn)[i] = v;
        }
        __syncthreads();

        // stage 1: T = relu(In @ W1 + b1)
        float acc[4][4];
        #pragma unroll
        for (int i = 0; i < 4; i++)
            #pragma unroll
            for (int j = 0; j < 4; j++) acc[i][j] = sB1[c0 + j];
        #pragma unroll 4
        for (int k = 0; k < HID; k++) {
            float4 w = *reinterpret_cast<const float4*>(&sW1[k * HID + c0]);
            #pragma unroll
            for (int i = 0; i < 4; i++) {
                float a = sIn[(r0 + i) * HID + k];
                acc[i][0] += a * w.x;
                acc[i][1] += a * w.y;
                acc[i][2] += a * w.z;
                acc[i][3] += a * w.w;
            }
        }
        #pragma unroll
        for (int i = 0; i < 4; i++) {
            float4 t;
            t.x = fmaxf(acc[i][0], 0.f);
            t.y = fmaxf(acc[i][1], 0.f);
            t.z = fmaxf(acc[i][2], 0.f);
            t.w = fmaxf(acc[i][3], 0.f);
            *reinterpret_cast<float4*>(&sT[(r0 + i) * HID + c0]) = t;
        }
        __syncthreads();

        // stage 2: z = T @ W2 + b2
        #pragma unroll
        for (int i = 0; i < 4; i++)
            #pragma unroll
            for (int j = 0; j < 4; j++) acc[i][j] = sB2[c0 + j];
        #pragma unroll 4
        for (int k = 0; k < HID; k++) {
            float4 w = *reinterpret_cast<const float4*>(&sW2[k * HID + c0]);
            #pragma unroll
            for (int i = 0; i < 4; i++) {
                float a = sT[(r0 + i) * HID + k];
                acc[i][0] += a * w.x;
                acc[i][1] += a * w.y;
                acc[i][2] += a * w.z;
                acc[i][3] += a * w.w;
            }
        }
        #pragma unroll
        for (int i = 0; i < 4; i++) {
            int row = rbase + r0 + i;
            if (row < rend) {
                float4 v = make_float4(acc[i][0], acc[i][1], acc[i][2], acc[i][3]);
                *reinterpret_cast<float4*>(&g_z[(size_t)row * HID + c0]) = v;
                #pragma unroll
                for (int j = 0; j < 4; j++) {
                    ls[j] += acc[i][j];
                    lss[j] += acc[i][j] * acc[i][j];
                }
            }
        }
        __syncthreads();
    }

    // block-level stats reduce in shared, one atomic per column per block
    #pragma unroll
    for (int j = 0; j < 4; j++) { sIn[tid * 4 + j] = ls[j]; sT[tid * 4 + j] = lss[j]; }
    __syncthreads();
    if (tid < HID) {
        int c = tid;
        float s = 0.f, ss = 0.f;
        #pragma unroll
        for (int w = 0; w < 16; w++) {
            int t = (c >> 2) + 32 * w;
            s += sIn[t * 4 + (c & 3)];
            ss += sT[t * 4 + (c & 3)];
        }
        atomicAdd(&g_stats[c], s);
        atomicAdd(&g_stats[HID + c], ss);
    }
}

// ---------------- BN finalize + apply + relu -> h ---------------------------
__global__ void bn_kernel(const float* __restrict__ gamma,
                          const float* __restrict__ beta) {
    int i = blockIdx.x * blockDim.x + threadIdx.x;  // float4 index
    const int n4 = N_NODES * HID / 4;
    if (i >= n4) return;
    int c0 = (i & 31) * 4;
    float4 v = reinterpret_cast<const float4*>(g_z)[i];
    float va[4] = {v.x, v.y, v.z, v.w};
    float out[4];
    const float invN = 1.0f / (float)N_NODES;
    #pragma unroll
    for (int j = 0; j < 4; j++) {
        int c = c0 + j;
        float mean = g_stats[c] * invN;
        float var = g_stats[HID + c] * invN - mean * mean;
        float rstd = rsqrtf(var + BN_EPS);
        float o = gamma[c] * (va[j] - mean) * rstd + beta[c];
        out[j] = fmaxf(o, 0.f);
    }
    reinterpret_cast<float4*>(g_h)[i] = make_float4(out[0], out[1], out[2], out[3]);
}

// ---------------- global add pool -------------------------------------------
__global__ void pool_kernel(const int* __restrict__ batch) {
    int i = blockIdx.x * blockDim.x + threadIdx.x;
    if (i >= N_NODES * 32) return;
    int n = i >> 5;
    int q = i & 31;
    int gi = batch[n];
    float4 v = reinterpret_cast<const float4*>(g_h + (size_t)n * HID)[q];
    red_add_v4(g_pool + (size_t)gi * HID + 4 * q, v);
}

// ---------------- head: out = relu(g@W1+b1)@W2+b2 ---------------------------
__global__ void head_kernel(const float* __restrict__ w1, const float* __restrict__ b1,
                            const float* __restrict__ w2, const float* __restrict__ b2,
                            float* __restrict__ out) {
    __shared__ float srow[HID];
    __shared__ float st[HID];
    int gi = blockIdx.x;
    int c = threadIdx.x;
    srow[c] = g_pool[(size_t)gi * HID + c];
    __syncthreads();
    float acc = b1[c];
    for (int k = 0; k < HID; k++) acc += srow[k] * w1[k * HID + c];
    st[c] = fmaxf(acc, 0.f);
    __syncthreads();
    if (c < 2) {
        float o = b2[c];
        for (int k = 0; k < HID; k++) o += st[k] * w2[k * 2 + c];
        out[gi * 2 + c] = o;
    }
}

// ---------------- launch -----------------------------------------------------
extern "C" void kernel_launch(void* const* d_in, const int* in_sizes, int n_in,
                              void* d_out, int out_size) {
    const float* x        = (const float*)d_in[0];
    const int*   eidx     = (const int*)d_in[1];
    const float* eattr    = (const float*)d_in[2];
    const int*   batch    = (const int*)d_in[3];
    const float* node_w   = (const float*)d_in[4];
    const float* node_b   = (const float*)d_in[5];
    const float* edge_w   = (const float*)d_in[6];
    const float* edge_b   = (const float*)d_in[7];
    const float* mlp_w1   = (const float*)d_in[8];
    const float* mlp_b1   = (const float*)d_in[9];
    const float* mlp_w2   = (const float*)d_in[10];
    const float* mlp_b2   = (const float*)d_in[11];
    const float* bn_gamma = (const float*)d_in[12];
    const float* bn_beta  = (const float*)d_in[13];
    const float* head_w1  = (const float*)d_in[14];
    const float* head_b1  = (const float*)d_in[15];
    const float* head_w2  = (const float*)d_in[16];
    const float* head_b2  = (const float*)d_in[17];
    float* out = (float*)d_out;

    const int mlp_smem = MLP_SMEM_FLOATS * (int)sizeof(float);
    cudaFuncSetAttribute(mlp_kernel, cudaFuncAttributeMaxDynamicSharedMemorySize, mlp_smem);

    // encoders (ea is layer-invariant -> computed once)
    encoder_kernel<<<512, 256>>>(x, node_w, node_b);
    edge_encoder_kernel<<<2048, 256>>>(eattr, edge_w, edge_b);

    // CSR build (by dst)
    zero_cnt_kernel<<<(N_NODES + 255) / 256, 256>>>();
    csr_count_kernel<<<(N_EDGES + 255) / 256, 256>>>(eidx);
    csr_scan_kernel<<<1, 1024>>>();
    csr_fill_kernel<<<(N_EDGES + 255) / 256, 256>>>(eidx);

    for (int l = 0; l < NLAYERS; l++) {
        zero_stats_kernel<<<1, 256>>>();
        agg_kernel<<<2048, 256>>>();
        mlp_kernel<<<148, MLP_THREADS, mlp_smem>>>(mlp_w1 + (size_t)l * HID * HID,
                                                   mlp_b1 + (size_t)l * HID,
                                                   mlp_w2 + (size_t)l * HID * HID,
                                                   mlp_b2 + (size_t)l * HID);
        bn_kernel<<<(N_NODES * HID / 4 + 255) / 256, 256>>>(bn_gamma + (size_t)l * HID,
                                                            bn_beta + (size_t)l * HID);
    }

    zero_pool_kernel<<<(NGRAPHS * HID + 255) / 256, 256>>>();
    pool_kernel<<<(N_NODES * 32 + 255) / 256, 256>>>(batch);
    head_kernel<<<NGRAPHS, HID>>>(head_w1, head_b1, head_w2, head_b2, out);
}